// round 14
// baseline (speedup 1.0000x reference)
#include <cuda_runtime.h>
#include <math.h>

#define D_FEAT 128
#define FULL 0xffffffffu
#define MAX_NODES 100000

// Scratch: per-node L2 norms of feature rows (allocation-free __device__ global).
__device__ float g_norms[MAX_NODES];

// ---------------------------------------------------------------------------
// Kernel 1: precompute ||features[n]|| for all nodes. Warp per node.
// DRAM-streaming bound (~6us) — at floor; also pre-warms L2 with the table.
// ---------------------------------------------------------------------------
__global__ void __launch_bounds__(256) norms_kernel(const float* __restrict__ feats,
                                                    int n_nodes) {
    int warp = (blockIdx.x * blockDim.x + threadIdx.x) >> 5;
    int lane = threadIdx.x & 31;
    if (warp >= n_nodes) return;
    const float4* row = (const float4*)(feats + (size_t)warp * D_FEAT);
    float4 v = row[lane];
    float s = v.x * v.x + v.y * v.y + v.z * v.z + v.w * v.w;
#pragma unroll
    for (int o = 16; o; o >>= 1) s += __shfl_xor_sync(FULL, s, o);
    if (lane == 0) g_norms[warp] = sqrtf(s);
}

__device__ __forceinline__ unsigned f2ord(float f) {
    unsigned u = __float_as_uint(f);
    return (u & 0x80000000u) ? ~u : (u | 0x80000000u);
}

__device__ __forceinline__ float dot4(float4 v, float4 c) {
    return v.x * c.x + v.y * c.y + v.z * c.z + v.w * c.w;
}

// Load 8 neighbor rows of group g and form per-lane partial dots.
__device__ __forceinline__ void group_dots(float (&p)[8], const int4* nb, int g,
                                           const float* feats, float4 c, int lane) {
    int4 ia = __ldg(&nb[2 * g]);
    int4 ib = __ldg(&nb[2 * g + 1]);
    p[0] = dot4(((const float4*)(feats + (size_t)ia.x * D_FEAT))[lane], c);
    p[1] = dot4(((const float4*)(feats + (size_t)ia.y * D_FEAT))[lane], c);
    p[2] = dot4(((const float4*)(feats + (size_t)ia.z * D_FEAT))[lane], c);
    p[3] = dot4(((const float4*)(feats + (size_t)ia.w * D_FEAT))[lane], c);
    p[4] = dot4(((const float4*)(feats + (size_t)ib.x * D_FEAT))[lane], c);
    p[5] = dot4(((const float4*)(feats + (size_t)ib.y * D_FEAT))[lane], c);
    p[6] = dot4(((const float4*)(feats + (size_t)ib.z * D_FEAT))[lane], c);
    p[7] = dot4(((const float4*)(feats + (size_t)ib.w * D_FEAT))[lane], c);
}

// Transpose-reduce 8 partials: afterwards the return value on lane l is the
// full 32-lane sum of original p[(l>>2)&7]. 9 shuffles, depth 5.
__device__ __forceinline__ float reduce8(float (&p)[8], bool h16, bool h8, bool h4) {
#pragma unroll
    for (int i = 0; i < 4; i++) {
        float send = h16 ? p[i] : p[i + 4];
        float recv = __shfl_xor_sync(FULL, send, 16);
        p[i] = (h16 ? p[i + 4] : p[i]) + recv;
    }
#pragma unroll
    for (int i = 0; i < 2; i++) {
        float send = h8 ? p[i] : p[i + 2];
        float recv = __shfl_xor_sync(FULL, send, 8);
        p[i] = (h8 ? p[i + 2] : p[i]) + recv;
    }
    {
        float send = h4 ? p[0] : p[1];
        float recv = __shfl_xor_sync(FULL, send, 4);
        p[0] = (h4 ? p[1] : p[0]) + recv;
    }
    p[0] += __shfl_xor_sync(FULL, p[0], 2);
    p[0] += __shfl_xor_sync(FULL, p[0], 1);
    return p[0];
}

// One selection step: pick current max key (lowest lane on ties), add to mask,
// knock out the winner.
__device__ __forceinline__ void sel_step(unsigned& key, unsigned& sel, int lane) {
    unsigned m = __reduce_max_sync(FULL, key);
    unsigned b = __ballot_sync(FULL, key == m);
    int kk = __ffs(b) - 1;
    sel |= 1u << kk;
    if (lane == kk) key = 0u;
}

// Masked-mean re-gather + relu + store for one node.
__device__ __forceinline__ void regather_store(const float* feats, float* out,
                                               unsigned sel, int myneigh,
                                               float inv, int lane, size_t b) {
    float4 acc = make_float4(0.f, 0.f, 0.f, 0.f);
    unsigned m2 = sel;
    while (m2) {
        int k = __ffs(m2) - 1;
        m2 &= m2 - 1;
        int idx = __shfl_sync(FULL, myneigh, k);
        const float4* row = (const float4*)(feats + (size_t)idx * D_FEAT);
        float4 v = row[lane];
        acc.x += v.x; acc.y += v.y; acc.z += v.z; acc.w += v.w;
    }
    float4 o;
    o.x = fmaxf(acc.x * inv, 0.0f);
    o.y = fmaxf(acc.y * inv, 0.0f);
    o.z = fmaxf(acc.z * inv, 0.0f);
    o.w = fmaxf(acc.w * inv, 0.0f);
    ((float4*)(out + b * D_FEAT))[lane] = o;
}

// ---------------------------------------------------------------------------
// Kernel 2: TWO batch nodes per warp (ILP=2). While node A's 9-shuffle
// reduction chain serializes, node B's 8 row loads are in flight, and vice
// versa — fills the latency gaps that capped issue at ~36% with 1 node/warp.
// Lane l permanently owns neighbor n(l) = 8*(l&3) + ((l>>2)&7) (where the
// group tree deposits its dot), so no redistribution shuffles.
// ---------------------------------------------------------------------------
__global__ void __launch_bounds__(256) agg_kernel(const float* __restrict__ feats,
                                                  const int* __restrict__ nodes,
                                                  const int* __restrict__ neighs,
                                                  const int* __restrict__ ns_ptr,
                                                  float* __restrict__ out,
                                                  int B, int K) {
    int warp = (blockIdx.x * blockDim.x + threadIdx.x) >> 5;
    int lane = threadIdx.x & 31;

    int ns = ns_ptr ? __ldg(ns_ptr) : 10;
    if (ns > K) ns = K;
    float inv = 1.0f / (float)ns;

    if (K == 32) {
        size_t bA = (size_t)warp * 2;
        size_t bB = bA + 1;
        if ((int)bA >= B) return;
        bool hasB = ((int)bB < B);

        int nodeA = __ldg(&nodes[bA]);
        int nodeB = hasB ? __ldg(&nodes[bB]) : nodeA;
        float cnA = g_norms[nodeA];
        float cnB = g_norms[nodeB];
        float4 cA = ((const float4*)(feats + (size_t)nodeA * D_FEAT))[lane];
        float4 cB = ((const float4*)(feats + (size_t)nodeB * D_FEAT))[lane];

        // Lane l owns neighbor n(l) = 8*(l&3) + ((l>>2)&7)  (fixed bijection).
        int nl = ((lane & 3) << 3) | ((lane >> 2) & 7);
        int neighA = __ldg(&neighs[bA * 32 + nl]);
        int neighB = hasB ? __ldg(&neighs[bB * 32 + nl]) : neighA;
        float nnA = g_norms[neighA];
        float nnB = g_norms[neighB];

        const int4* nbA = (const int4*)(neighs + bA * 32);
        const int4* nbB = (const int4*)(neighs + bB * 32);

        bool h16 = (lane & 16) != 0;
        bool h8  = (lane & 8)  != 0;
        bool h4  = (lane & 4)  != 0;
        int gown = lane & 3;
        float dotA = 0.0f, dotB = 0.0f;
#pragma unroll
        for (int g = 0; g < 4; g++) {
            float pA[8], pB[8];
            group_dots(pA, nbA, g, feats, cA, lane);
            group_dots(pB, nbB, g, feats, cB, lane);   // B loads fly under A's chain
            float rA = reduce8(pA, h16, h8, h4);
            float rB = reduce8(pB, h16, h8, h4);
            if (gown == g) { dotA = rA; dotB = rB; }
        }
        float simA = dotA / (cnA * nnA);
        float simB = dotB / (cnB * nnB);

        // --- two interleaved top-ns selections (independent redux chains) ---
        unsigned keyA = f2ord(simA);
        unsigned keyB = f2ord(simB);
        unsigned selA = 0u, selB = 0u;
        if (hasB) {
            for (int i = 0; i < ns; i++) {
                sel_step(keyA, selA, lane);
                sel_step(keyB, selB, lane);
            }
        } else {
            for (int i = 0; i < ns; i++) sel_step(keyA, selA, lane);
        }

        // --- masked mean + relu, per node ---
        regather_store(feats, out, selA, neighA, inv, lane, bA);
        if (hasB) regather_store(feats, out, selB, neighB, inv, lane, bB);
    } else {
        // generic fallback: one node per warp position, two sequentially
        for (int t = 0; t < 2; t++) {
            size_t b = (size_t)warp * 2 + t;
            if ((int)b >= B) return;
            int node = __ldg(&nodes[b]);
            float cnorm = g_norms[node];
            float4 c = ((const float4*)(feats + (size_t)node * D_FEAT))[lane];
            int myneigh = (lane < K) ? __ldg(&neighs[b * K + lane]) : 0;
            float mynorm = g_norms[myneigh];
            float mydot = 0.0f;
            for (int k = 0; k < K; k++) {
                int idx = __shfl_sync(FULL, myneigh, k);
                const float4* row = (const float4*)(feats + (size_t)idx * D_FEAT);
                float pp = dot4(row[lane], c);
#pragma unroll
                for (int o = 16; o; o >>= 1) pp += __shfl_xor_sync(FULL, pp, o);
                if (lane == k) mydot = pp;
            }
            float sim = mydot / (cnorm * mynorm);
            unsigned key = f2ord(sim);
            if (lane >= K) key = 0u;
            unsigned sel = 0u;
            for (int i = 0; i < ns; i++) sel_step(key, sel, lane);
            regather_store(feats, out, sel, myneigh, inv, lane, b);
        }
    }
}

// ---------------------------------------------------------------------------
// kernel_launch: graph-capturable, allocation-free.
// ---------------------------------------------------------------------------
extern "C" void kernel_launch(void* const* d_in, const int* in_sizes, int n_in,
                              void* d_out, int out_size) {
    const float* feats = (const float*)d_in[0];
    const int* nodes = (const int*)d_in[1];
    const int* neighs = (const int*)d_in[2];
    const int* ns_ptr = (n_in > 3) ? (const int*)d_in[3] : nullptr;

    int n_nodes = in_sizes[0] / D_FEAT;
    if (n_nodes > MAX_NODES) n_nodes = MAX_NODES;
    int B = in_sizes[1];
    int K = (B > 0) ? (in_sizes[2] / B) : 0;

    int norm_blocks = (n_nodes * 32 + 255) / 256;
    norms_kernel<<<norm_blocks, 256>>>(feats, n_nodes);

    // two nodes per warp
    int nwarps = (B + 1) / 2;
    int agg_blocks = (nwarps * 32 + 255) / 256;
    agg_kernel<<<agg_blocks, 256>>>(feats, nodes, neighs, ns_ptr,
                                    (float*)d_out, B, K);
}